// round 9
// baseline (speedup 1.0000x reference)
#include <cuda_runtime.h>
#include <cuda_fp16.h>
#include <cstdint>

// ---------------------------------------------------------------------------
// Problem constants
// ---------------------------------------------------------------------------
#define NRr     2000
#define NPp     1512
#define NTOT    3512
#define DTOT    512
#define BATCH   8192
#define FLATN   8192
#define KATT    3000
#define KATT_T  3008
#define KFUN    5603
#define KFUN_T  5632

// Scratch (device globals; allocation is forbidden)
__device__ __half g_ah_att[(size_t)NTOT * KATT_T];
__device__ __half g_ah_fun[(size_t)NTOT * KFUN_T];
__device__ __half g_wt1a [(size_t)2048 * KATT_T];
__device__ __half g_wt1f [(size_t)4096 * KFUN_T];
__device__ __half g_wt2a [(size_t)256 * 2048];
__device__ __half g_wt2f [(size_t)256 * 4096];
__device__ __half g_h_att[(size_t)NTOT * 2048];
__device__ __half g_h_fun[(size_t)NTOT * 4096];

// ---------------------------------------------------------------------------
// helpers
// ---------------------------------------------------------------------------
__device__ __forceinline__ float tanh_fast(float x) {
    float r;
    asm("tanh.approx.f32 %0, %1;" : "=f"(r) : "f"(x));
    return r;
}

__device__ __forceinline__ void mma16(float* d, const uint32_t* a, const uint32_t* b) {
    asm volatile(
        "mma.sync.aligned.m16n8k16.row.col.f32.f16.f16.f32 "
        "{%0,%1,%2,%3},{%4,%5,%6,%7},{%8,%9},{%0,%1,%2,%3};"
        : "+f"(d[0]), "+f"(d[1]), "+f"(d[2]), "+f"(d[3])
        : "r"(a[0]), "r"(a[1]), "r"(a[2]), "r"(a[3]), "r"(b[0]), "r"(b[1]));
}

__device__ __forceinline__ void ldsm4(uint32_t& r0, uint32_t& r1,
                                      uint32_t& r2, uint32_t& r3, uint32_t addr) {
    asm volatile("ldmatrix.sync.aligned.m8n8.x4.shared.b16 {%0,%1,%2,%3}, [%4];"
                 : "=r"(r0), "=r"(r1), "=r"(r2), "=r"(r3) : "r"(addr));
}

__device__ __forceinline__ void cpa16h(__half* smem_dst, const __half* g, bool pred) {
    uint32_t s = (uint32_t)__cvta_generic_to_shared(smem_dst);
    int sz = pred ? 16 : 0;
    asm volatile("cp.async.cg.shared.global [%0], [%1], 16, %2;"
                 :: "r"(s), "l"(g), "r"(sz));
}

__device__ __forceinline__ float lrelu(float v) {
    return v >= 0.f ? v : 0.01f * v;
}

__device__ __forceinline__ uint32_t smem_u32(const void* p) {
    return (uint32_t)__cvta_generic_to_shared(p);
}

// ---------------------------------------------------------------------------
// Prepasses
// ---------------------------------------------------------------------------
__global__ void cvtA(const float* __restrict__ r, const float* __restrict__ p,
                     int nr, int Kin, __half* __restrict__ dst, int KT)
{
    int row = blockIdx.y;
    int c = blockIdx.x * 256 + threadIdx.x;
    if (c >= KT) return;
    const float* s = (row < nr) ? (r + (size_t)row * Kin)
                                : (p + (size_t)(row - nr) * Kin);
    dst[(size_t)row * KT + c] = (c < Kin) ? __float2half_rn(s[c]) : __half(0.f);
}

__global__ void transpose_h(const float* __restrict__ W, __half* __restrict__ WT,
                            int K, int N, int KT)
{
    __shared__ float t[32][33];
    int k0 = blockIdx.y * 32, n0 = blockIdx.x * 32;
    #pragma unroll
    for (int r = threadIdx.y; r < 32; r += 8) {
        int k = k0 + r;
        t[r][threadIdx.x] = (k < K) ? W[(size_t)k * N + n0 + threadIdx.x] : 0.f;
    }
    __syncthreads();
    #pragma unroll
    for (int r = threadIdx.y; r < 32; r += 8) {
        int n = n0 + r, k = k0 + threadIdx.x;
        WT[(size_t)n * KT + k] = __float2half_rn(t[threadIdx.x][r]);
    }
}

// ---------------------------------------------------------------------------
// Layer-1 FP16 GEMM: BM=128, BN=256, warp grid 2x4, warp tile 64x64.
// C[m,n] = gelu(sum_k A[m,k]*BT[n,k] + bias[n]), half out.
// 3-stage cp.async, ldmatrix fragments. KT % 32 == 0, N % 256 == 0.
// ---------------------------------------------------------------------------
__global__ __launch_bounds__(256)
void gemm1_h(const __half* __restrict__ A, int lda, int M, int N, int KT,
             const __half* __restrict__ BT, int ldb,
             const float* __restrict__ bias,
             __half* __restrict__ C, int ldc)
{
    constexpr int ST = 3;
    constexpr int ASZ = 128 * 40;    // halves
    constexpr int BSZ = 256 * 40;    // halves

    extern __shared__ __half hsm[];
    __half* Ash = hsm;
    __half* Bsh = hsm + ST * ASZ;

    const int tid  = threadIdx.x;
    const int lane = tid & 31, warp = tid >> 5;
    const int wm = warp >> 2, wn = warp & 3;
    const int bm = blockIdx.y * 128, bn = blockIdx.x * 256;

    float acc[4][8][4];
    #pragma unroll
    for (int i = 0; i < 4; ++i)
        #pragma unroll
        for (int j = 0; j < 8; ++j)
            #pragma unroll
            for (int q = 0; q < 4; ++q) acc[i][j][q] = 0.f;

    const int nIt = KT / 32;
    const int arr = tid >> 2;            // 0..63
    const int ac8 = (tid & 3) * 8;

    const int lmA_row  = lane & 15;
    const int lmA_koff = (lane >> 4) * 8;
    const int lmB_n    = (lane & 7) + ((lane >> 4) & 1) * 8;
    const int lmB_koff = ((lane >> 3) & 1) * 8;

    const uint32_t ash0 = smem_u32(Ash);
    const uint32_t bsh0 = smem_u32(Bsh);

    auto load_stage = [&](int st, int kt) {
        __half* as = Ash + st * ASZ;
        __half* bs = Bsh + st * BSZ;
        #pragma unroll
        for (int u = 0; u < 2; ++u) {
            int r = arr + u * 64;
            int m = bm + r;
            bool p = (m < M);
            cpa16h(&as[r * 40 + ac8], A + (size_t)(p ? m : 0) * lda + kt + ac8, p);
        }
        #pragma unroll
        for (int u = 0; u < 4; ++u) {
            int n = arr + u * 64;
            cpa16h(&bs[n * 40 + ac8], BT + (size_t)(bn + n) * ldb + kt + ac8, true);
        }
        asm volatile("cp.async.commit_group;");
    };

    load_stage(0, 0);
    load_stage(1, 32);

    for (int it = 0; it < nIt; ++it) {
        const int cur = it % ST;
        asm volatile("cp.async.wait_group 1;");
        __syncthreads();

        int nx = it + ST - 1;
        if (nx < nIt) load_stage(nx % ST, nx * 32);
        else          asm volatile("cp.async.commit_group;");

        const uint32_t asb = ash0 + cur * ASZ * 2;
        const uint32_t bsb = bsh0 + cur * BSZ * 2;
        #pragma unroll
        for (int kk = 0; kk < 2; ++kk) {
            uint32_t af[4][4];
            #pragma unroll
            for (int mi = 0; mi < 4; ++mi) {
                int r0 = wm * 64 + mi * 16;
                uint32_t addr = asb +
                    (uint32_t)(((r0 + lmA_row) * 40 + lmA_koff + kk * 16) * 2);
                ldsm4(af[mi][0], af[mi][1], af[mi][2], af[mi][3], addr);
            }
            uint32_t bf[8][2];
            #pragma unroll
            for (int np = 0; np < 4; ++np) {
                int n0 = wn * 64 + np * 16;
                uint32_t addr = bsb +
                    (uint32_t)(((n0 + lmB_n) * 40 + lmB_koff + kk * 16) * 2);
                ldsm4(bf[2 * np][0], bf[2 * np][1],
                      bf[2 * np + 1][0], bf[2 * np + 1][1], addr);
            }
            #pragma unroll
            for (int mi = 0; mi < 4; ++mi)
                #pragma unroll
                for (int ni = 0; ni < 8; ++ni)
                    mma16(acc[mi][ni], af[mi], bf[ni]);
        }
        __syncthreads();
    }

    // epilogue: bias + exact gelu, half2 stores
    #pragma unroll
    for (int mi = 0; mi < 4; ++mi) {
        #pragma unroll
        for (int ni = 0; ni < 8; ++ni) {
            int m0 = bm + wm * 64 + mi * 16 + (lane >> 2);
            int n  = bn + wn * 64 + ni * 8 + (lane & 3) * 2;
            float bi0 = bias[n], bi1 = bias[n + 1];
            #pragma unroll
            for (int h = 0; h < 2; ++h) {
                int m = m0 + h * 8;
                if (m < M) {
                    float v0 = acc[mi][ni][h * 2 + 0] + bi0;
                    float v1 = acc[mi][ni][h * 2 + 1] + bi1;
                    v0 = 0.5f * v0 * (1.f + erff(v0 * 0.70710678118654752f));
                    v1 = 0.5f * v1 * (1.f + erff(v1 * 0.70710678118654752f));
                    *(__half2*)&C[(size_t)m * ldc + n] = __floats2half2_rn(v0, v1);
                }
            }
        }
    }
}

// ---------------------------------------------------------------------------
// Layer-2 FP16 GEMM (BM=64, BN=128), sigmoid, float out
// ---------------------------------------------------------------------------
__global__ __launch_bounds__(256, 2)
void gemm2_h(const __half* __restrict__ A, int lda, int M, int N, int KT,
             const __half* __restrict__ BT, int ldb,
             const float* __restrict__ bias,
             float* __restrict__ C, int ldc, int coloff)
{
    constexpr int ST = 3, BM = 64;
    constexpr int WM = BM / 4;
    constexpr int MI = WM / 16;
    constexpr int ASZ = BM * 40;
    constexpr int BSZ = 128 * 40;

    extern __shared__ __half hsm[];
    __half* Ash = hsm;
    __half* Bsh = hsm + ST * ASZ;

    const int tid  = threadIdx.x;
    const int lane = tid & 31, warp = tid >> 5;
    const int wm = warp >> 1, wn = warp & 1;
    const int bm = blockIdx.y * BM, bn = blockIdx.x * 128;

    float acc[MI][8][4];
    #pragma unroll
    for (int i = 0; i < MI; ++i)
        #pragma unroll
        for (int j = 0; j < 8; ++j)
            #pragma unroll
            for (int q = 0; q < 4; ++q) acc[i][j][q] = 0.f;

    const int nIt = KT / 32;
    const int arr = tid >> 2;
    const int ac8 = (tid & 3) * 8;

    const int lmA_row  = lane & 15;
    const int lmA_koff = (lane >> 4) * 8;
    const int lmB_n    = (lane & 7) + ((lane >> 4) & 1) * 8;
    const int lmB_koff = ((lane >> 3) & 1) * 8;

    const uint32_t ash0 = smem_u32(Ash);
    const uint32_t bsh0 = smem_u32(Bsh);

    auto load_stage = [&](int st, int kt) {
        __half* as = Ash + st * ASZ;
        __half* bs = Bsh + st * BSZ;
        int m = bm + arr;
        bool p = (m < M);
        cpa16h(&as[arr * 40 + ac8], A + (size_t)(p ? m : 0) * lda + kt + ac8, p);
        #pragma unroll
        for (int u = 0; u < 2; ++u) {
            int n = arr + u * 64;
            cpa16h(&bs[n * 40 + ac8], BT + (size_t)(bn + n) * ldb + kt + ac8, true);
        }
        asm volatile("cp.async.commit_group;");
    };

    load_stage(0, 0);
    load_stage(1, 32);

    for (int it = 0; it < nIt; ++it) {
        const int cur = it % ST;
        asm volatile("cp.async.wait_group 1;");
        __syncthreads();

        int nx = it + ST - 1;
        if (nx < nIt) load_stage(nx % ST, nx * 32);
        else          asm volatile("cp.async.commit_group;");

        const uint32_t asb = ash0 + cur * ASZ * 2;
        const uint32_t bsb = bsh0 + cur * BSZ * 2;
        #pragma unroll
        for (int kk = 0; kk < 2; ++kk) {
            uint32_t af[MI][4];
            #pragma unroll
            for (int mi = 0; mi < MI; ++mi) {
                int r0 = wm * WM + mi * 16;
                uint32_t addr = asb +
                    (uint32_t)(((r0 + lmA_row) * 40 + lmA_koff + kk * 16) * 2);
                ldsm4(af[mi][0], af[mi][1], af[mi][2], af[mi][3], addr);
            }
            uint32_t bf[8][2];
            #pragma unroll
            for (int np = 0; np < 4; ++np) {
                int n0 = wn * 64 + np * 16;
                uint32_t addr = bsb +
                    (uint32_t)(((n0 + lmB_n) * 40 + lmB_koff + kk * 16) * 2);
                ldsm4(bf[2 * np][0], bf[2 * np][1],
                      bf[2 * np + 1][0], bf[2 * np + 1][1], addr);
            }
            #pragma unroll
            for (int mi = 0; mi < MI; ++mi)
                #pragma unroll
                for (int ni = 0; ni < 8; ++ni)
                    mma16(acc[mi][ni], af[mi], bf[ni]);
        }
        __syncthreads();
    }

    #pragma unroll
    for (int mi = 0; mi < MI; ++mi) {
        #pragma unroll
        for (int ni = 0; ni < 8; ++ni) {
            int m0 = bm + wm * WM + mi * 16 + (lane >> 2);
            int n  = bn + wn * 64 + ni * 8 + (lane & 3) * 2;
            float bi0 = bias[n], bi1 = bias[n + 1];
            #pragma unroll
            for (int h = 0; h < 2; ++h) {
                int m = m0 + h * 8;
                if (m < M) {
                    float v0 = acc[mi][ni][h * 2 + 0] + bi0;
                    float v1 = acc[mi][ni][h * 2 + 1] + bi1;
                    v0 = 1.f / (1.f + __expf(-v0));
                    v1 = 1.f / (1.f + __expf(-v1));
                    *(float2*)&C[(size_t)m * ldc + coloff + n] = make_float2(v0, v1);
                }
            }
        }
    }
}

// ---------------------------------------------------------------------------
// Fused conv head (R6, passing): conv1 scalar, conv2 valid-ki-only fp16 MMA
// ---------------------------------------------------------------------------
__global__ __launch_bounds__(256)
void conv_head(const float* __restrict__ e,
               const int* __restrict__ idx,
               const float* __restrict__ w1, const float* __restrict__ b1,
               const float* __restrict__ w2, const float* __restrict__ b2,
               const float* __restrict__ Wout, const float* __restrict__ bout,
               float* __restrict__ outp,
               float* __restrict__ flat)
{
    extern __shared__ float sm[];
    float* w1s  = sm;                          // 240
    float* xs   = sm + 240;                    // 1040
    float* red  = sm + 1280;                   // 16
    float* pool = sm + 1296;                   // 8448
    uint32_t* w2h2 = (uint32_t*)(sm + 9744);   // 32 x 148 half2
    uint32_t* h1d  = (uint32_t*)(sm + 14480);  // 33 x 265 half2
    __half* w2h = (__half*)w2h2;
    __half* h1h = (__half*)h1d;

    const int tid = threadIdx.x;
    const int lane = tid & 31, w = tid >> 5;
    const int b = blockIdx.x;

    for (int i = tid; i < 240; i += 256) w1s[i] = w1[i];
    for (int i = tid; i < 32 * 296; i += 256) {
        int o = i / 296, k2 = i - o * 296;
        float v = 0.f;
        if (k2 < 288) {
            int ki = k2 / 96, rem = k2 - ki * 96;
            int c = rem / 6, kj = rem - c * 6;
            if (kj < 5) v = w2[o * 240 + c * 15 + ki * 5 + kj];
        }
        w2h[o * 296 + k2] = __float2half_rn(v);
    }
    for (int i = tid; i < 1040; i += 256) xs[i] = 0.f;
    for (int i = tid; i < 33 * 265; i += 256) h1d[i] = 0u;
    __syncthreads();

    const int iv   = idx[b];
    const int r_no = iv / 1512;
    const int p_no = iv - r_no * 1512;
    const float* er = e + (size_t)r_no * DTOT;
    const float* ep = e + (size_t)(NRr + p_no) * DTOT;
    for (int i = tid; i < DTOT; i += 256) {
        xs[2 + i]       = er[i];
        xs[520 + 2 + i] = ep[i];
    }
    __syncthreads();

    {
        const int q  = tid;
        const int j0 = 2 * q;
        const int jc = 2 + q;
        for (int c = 0; c < 16; ++c) {
            float W0[5], W1[5], W2[5];
            #pragma unroll
            for (int kj = 0; kj < 5; ++kj) {
                W0[kj] = w1s[c * 15 + kj];
                W1[kj] = w1s[c * 15 + 5 + kj];
                W2[kj] = w1s[c * 15 + 10 + kj];
            }
            float X0[6], X1[6];
            #pragma unroll
            for (int t = 0; t < 6; ++t) {
                X0[t] = xs[j0 + t];
                X1[t] = xs[520 + j0 + t];
            }
            const float bb = b1[c];
            float v00 = bb, v01 = bb, v10 = bb, v11 = bb;
            float v20 = bb, v21 = bb, v30 = bb, v31 = bb;
            #pragma unroll
            for (int kj = 0; kj < 5; ++kj) {
                v00 = fmaf(W2[kj], X0[kj],     v00);
                v01 = fmaf(W2[kj], X0[kj + 1], v01);
                v10 = fmaf(W1[kj], X0[kj],     v10);
                v10 = fmaf(W2[kj], X1[kj],     v10);
                v11 = fmaf(W1[kj], X0[kj + 1], v11);
                v11 = fmaf(W2[kj], X1[kj + 1], v11);
                v20 = fmaf(W0[kj], X0[kj],     v20);
                v20 = fmaf(W1[kj], X1[kj],     v20);
                v21 = fmaf(W0[kj], X0[kj + 1], v21);
                v21 = fmaf(W1[kj], X1[kj + 1], v21);
                v30 = fmaf(W0[kj], X1[kj],     v30);
                v31 = fmaf(W0[kj], X1[kj + 1], v31);
            }
            float p0 = 0.25f * (lrelu(v00) + lrelu(v01) + lrelu(v10) + lrelu(v11));
            float p1 = 0.25f * (lrelu(v20) + lrelu(v21) + lrelu(v30) + lrelu(v31));
            __half h0 = __float2half_rn(p0);
            __half h1v = __float2half_rn(p1);
            int r0 = (c * 2 + 0) * 530, r1 = (c * 2 + 1) * 530;
            h1h[r0 + 2 * jc]     = h0;
            h1h[r0 + 2 * jc - 1] = h0;
            h1h[r1 + 2 * jc]     = h1v;
            h1h[r1 + 2 * jc - 1] = h1v;
        }
    }
    __syncthreads();

    float acc[8][4][4];
    #pragma unroll
    for (int nt = 0; nt < 4; ++nt) {
        int o = nt * 8 + 2 * (lane & 3);
        float q0 = b2[o], q1 = b2[o + 1];
        #pragma unroll
        for (int u = 0; u < 8; ++u) {
            acc[u][nt][0] = q0; acc[u][nt][1] = q1;
            acc[u][nt][2] = q0; acc[u][nt][3] = q1;
        }
    }

    const int kq = lane & 3;
    const int col_lo = (w << 4) + (lane >> 2);
    const int col_hi = ((w + 8) << 4) + (lane >> 2);

    #pragma unroll
    for (int ki = 0; ki < 3; ++ki) {
        const int u0 = (2 - ki) * 2;
        #pragma unroll
        for (int s = 0; s < 6; ++s) {
            const int klo = s * 16 + kq * 2;
            const int khi = klo + 8;
            const int c0 = klo / 6, ol0 = klo - c0 * 6;
            const int c1 = khi / 6, ol1 = khi - c1 * 6;
            const int kb = ki * 48 + s * 8 + kq;

            uint32_t bf[4][2];
            #pragma unroll
            for (int nt = 0; nt < 4; ++nt) {
                int n = nt * 8 + (lane >> 2);
                bf[nt][0] = w2h2[n * 148 + kb];
                bf[nt][1] = w2h2[n * 148 + kb + 4];
            }
            #pragma unroll
            for (int v = 0; v < 4; ++v) {
                const int u = u0 + v;
                const int r = v >> 1;
                const int row0 = c0 * 2 + r;
                const int row1 = c1 * 2 + r;
                const int col = (u & 1) ? col_hi : col_lo;
                uint32_t a[4];
                a[0] = h1d[row0 * 265 + col + ol0];
                a[1] = h1d[row0 * 265 + col + 8 + ol0];
                a[2] = h1d[row1 * 265 + col + ol1];
                a[3] = h1d[row1 * 265 + col + 8 + ol1];
                #pragma unroll
                for (int nt = 0; nt < 4; ++nt)
                    mma16(acc[u][nt], a, bf[nt]);
            }
        }
    }

    const bool act = ((lane >> 2) & 1) == 0;
    const int jp = lane >> 3;
    #pragma unroll
    for (int uu = 0; uu < 4; ++uu) {
        int u  = (uu & 1) + (uu >> 1) * 4;
        int ip = (u >= 4);
        int jb = (((u & 1) ? w + 8 : w) << 3);
        #pragma unroll
        for (int nt = 0; nt < 4; ++nt) {
            int o = nt * 8 + 2 * (lane & 3);
            float v[4];
            #pragma unroll
            for (int q = 0; q < 4; ++q) {
                float x = lrelu(acc[u][nt][q]);
                float y = lrelu(acc[u + 2][nt][q]);
                x = fmaxf(x, y);
                float z = __shfl_xor_sync(0xffffffffu, x, 4);
                v[q] = fmaxf(x, z);
            }
            if (act) {
                int base  = (ip * 128 + jb + jp) * 33;
                int base2 = base + 4 * 33;
                pool[base  + o]     = tanh_fast(v[0]);
                pool[base  + o + 1] = tanh_fast(v[1]);
                pool[base2 + o]     = tanh_fast(v[2]);
                pool[base2 + o + 1] = tanh_fast(v[3]);
            }
        }
    }
    __syncthreads();

    float d0 = 0.f, d1 = 0.f;
    float* fb = flat + (size_t)b * FLATN;
    const float2* Wo2 = (const float2*)Wout;
    #pragma unroll
    for (int g = 0; g < 32; ++g) {
        float v = pool[tid * 33 + g];
        int k = g * 256 + tid;
        fb[k] = v;
        float2 wv = __ldg(Wo2 + k);
        d0 = fmaf(v, wv.x, d0);
        d1 = fmaf(v, wv.y, d1);
    }
    #pragma unroll
    for (int off = 16; off > 0; off >>= 1) {
        d0 += __shfl_down_sync(0xffffffffu, d0, off);
        d1 += __shfl_down_sync(0xffffffffu, d1, off);
    }
    if (lane == 0) { red[w * 2] = d0; red[w * 2 + 1] = d1; }
    __syncthreads();
    if (tid == 0) {
        float s0 = 0.f, s1 = 0.f;
        #pragma unroll
        for (int i = 0; i < 8; ++i) { s0 += red[i * 2]; s1 += red[i * 2 + 1]; }
        outp[(size_t)b * 2 + 0] = s0 + bout[0];
        outp[(size_t)b * 2 + 1] = s1 + bout[1];
    }
}

// ---------------------------------------------------------------------------
// kernel_launch — att chain on side stream, fun chain + conv on main stream
// ---------------------------------------------------------------------------
extern "C" void kernel_launch(void* const* d_in, const int* in_sizes, int n_in,
                              void* d_out, int out_size)
{
    const float* r_att   = (const float*)d_in[0];
    const float* p_att   = (const float*)d_in[1];
    const float* r_fun   = (const float*)d_in[2];
    const float* p_fun   = (const float*)d_in[3];
    const int*   idx     = (const int*)  d_in[4];
    const float* W_att1  = (const float*)d_in[5];
    const float* b_att1  = (const float*)d_in[6];
    const float* W_att2  = (const float*)d_in[7];
    const float* b_att2  = (const float*)d_in[8];
    const float* W_fun1  = (const float*)d_in[9];
    const float* b_fun1  = (const float*)d_in[10];
    const float* W_fun2  = (const float*)d_in[11];
    const float* b_fun2  = (const float*)d_in[12];
    const float* conv1_w = (const float*)d_in[13];
    const float* conv1_b = (const float*)d_in[14];
    const float* conv2_w = (const float*)d_in[15];
    const float* conv2_b = (const float*)d_in[16];
    const float* W_out   = (const float*)d_in[17];
    const float* b_out   = (const float*)d_in[18];

    float* out  = (float*)d_out;
    float* e    = out;
    float* outp = out + (size_t)NTOT * DTOT;
    float* flat = outp + (size_t)BATCH * 2;

    __half *ahA, *ahF, *wt1a, *wt1f, *wt2a, *wt2f, *hA, *hF;
    cudaGetSymbolAddress((void**)&ahA,  g_ah_att);
    cudaGetSymbolAddress((void**)&ahF,  g_ah_fun);
    cudaGetSymbolAddress((void**)&wt1a, g_wt1a);
    cudaGetSymbolAddress((void**)&wt1f, g_wt1f);
    cudaGetSymbolAddress((void**)&wt2a, g_wt2a);
    cudaGetSymbolAddress((void**)&wt2f, g_wt2f);
    cudaGetSymbolAddress((void**)&hA,   g_h_att);
    cudaGetSymbolAddress((void**)&hF,   g_h_fun);

    static cudaStream_t s_att = nullptr;
    static cudaEvent_t  ev0 = nullptr, evA = nullptr;
    if (!s_att) {
        cudaStreamCreateWithFlags(&s_att, cudaStreamNonBlocking);
        cudaEventCreateWithFlags(&ev0, cudaEventDisableTiming);
        cudaEventCreateWithFlags(&evA, cudaEventDisableTiming);
    }

    const int smG1  = 3 * (128 * 40 + 256 * 40) * 2;    // 92160 B
    const int smG64 = 3 * (64 * 40 + 128 * 40) * 2;     // 46080 B
    cudaFuncSetAttribute(gemm1_h,
                         cudaFuncAttributeMaxDynamicSharedMemorySize, smG1);
    cudaFuncSetAttribute(gemm2_h,
                         cudaFuncAttributeMaxDynamicSharedMemorySize, smG64);
    const int smC = (9744 + 4736 + 8745) * 4;           // 92900 B
    cudaFuncSetAttribute(conv_head,
                         cudaFuncAttributeMaxDynamicSharedMemorySize, smC);

    // fork
    cudaEventRecord(ev0, 0);
    cudaStreamWaitEvent(s_att, ev0, 0);

    // ---- att chain (side stream) ----
    cvtA<<<dim3((KATT_T + 255) / 256, NTOT), 256, 0, s_att>>>(
        r_att, p_att, NRr, KATT, ahA, KATT_T);
    transpose_h<<<dim3(2048 / 32, KATT_T / 32), dim3(32, 8), 0, s_att>>>(
        W_att1, wt1a, KATT, 2048, KATT_T);
    transpose_h<<<dim3(256 / 32, 2048 / 32), dim3(32, 8), 0, s_att>>>(
        W_att2, wt2a, 2048, 256, 2048);
    gemm1_h<<<dim3(2048 / 256, (NTOT + 127) / 128), 256, smG1, s_att>>>(
        ahA, KATT_T, NTOT, 2048, KATT_T, wt1a, KATT_T, b_att1, hA, 2048);
    gemm2_h<<<dim3(256 / 128, (NTOT + 63) / 64), 256, smG64, s_att>>>(
        hA, 2048, NTOT, 256, 2048, wt2a, 2048, b_att2, e, DTOT, 0);
    cudaEventRecord(evA, s_att);

    // ---- fun chain (main stream) ----
    cvtA<<<dim3((KFUN_T + 255) / 256, NTOT), 256>>>(
        r_fun, p_fun, NRr, KFUN, ahF, KFUN_T);
    transpose_h<<<dim3(4096 / 32, KFUN_T / 32), dim3(32, 8)>>>(
        W_fun1, wt1f, KFUN, 4096, KFUN_T);
    transpose_h<<<dim3(256 / 32, 4096 / 32), dim3(32, 8)>>>(
        W_fun2, wt2f, 4096, 256, 4096);
    gemm1_h<<<dim3(4096 / 256, (NTOT + 127) / 128), 256, smG1>>>(
        ahF, KFUN_T, NTOT, 4096, KFUN_T, wt1f, KFUN_T, b_fun1, hF, 4096);
    gemm2_h<<<dim3(256 / 128, (NTOT + 63) / 64), 256, smG64>>>(
        hF, 4096, NTOT, 256, 4096, wt2f, 4096, b_fun2, e, DTOT, 256);

    // join, then conv head
    cudaStreamWaitEvent(0, evA, 0);
    conv_head<<<BATCH, 256, smC>>>(
        e, idx, conv1_w, conv1_b, conv2_w, conv2_b, W_out, b_out, outp, flat);
}